// round 2
// baseline (speedup 1.0000x reference)
#include <cuda_runtime.h>

#define NA    100000
#define NEDGE 200000
#define HID   512
#define AD    133
#define BD    14
#define KIN   147   // AD + BD
#define KOUT  645   // AD + HID

// ---------------- scratch (static device globals; no allocation) ------------
__device__ float g_h0 [(size_t)NEDGE * HID];
__device__ float g_hA [(size_t)NEDGE * HID];
__device__ float g_hB [(size_t)NEDGE * HID];
__device__ float g_agg[(size_t)NA    * HID];

// ---------------- utility kernels ------------------------------------------
__global__ void zero_k(float4* __restrict__ p, int n4) {
    int i = blockIdx.x * blockDim.x + threadIdx.x;
    if (i < n4) p[i] = make_float4(0.f, 0.f, 0.f, 0.f);
}

// agg[dst[e]] += w[e] * h[e]   (weighted; wgt==nullptr -> w=1)
__global__ void scatter_k(const float* __restrict__ h,
                          const int* __restrict__ dst,
                          const float* __restrict__ wgt,
                          float* __restrict__ agg) {
    int idx = blockIdx.x * blockDim.x + threadIdx.x;      // NEDGE * 128 threads
    if (idx >= NEDGE * 128) return;
    int e = idx >> 7;
    int c = (idx & 127) << 2;
    int d = dst[e];
    float w = wgt ? wgt[e] : 1.0f;
    float4 hv = *(const float4*)(h + (size_t)e * HID + c);
    float* a = agg + (size_t)d * HID + c;
    atomicAdd(a + 0, w * hv.x);
    atomicAdd(a + 1, w * hv.y);
    atomicAdd(a + 2, w * hv.z);
    atomicAdd(a + 3, w * hv.w);
}

__global__ void batch_k(const int* __restrict__ b, float* __restrict__ out) {
    int i = blockIdx.x * blockDim.x + threadIdx.x;
    if (i < NA) out[i] = (float)b[i];
}

__global__ void copy4_k(const float4* __restrict__ src, float4* __restrict__ dst, int n4) {
    int i = blockIdx.x * blockDim.x + threadIdx.x;
    if (i < n4) dst[i] = src[i];
}

// ---------------- fused SGEMM -----------------------------------------------
// C[M,512] = relu( A @ W^T (+ add) )
// MODE 1: A row e = [V[src[e]] ; E[e]]                          K=147
// MODE 2: A row e = agg[src[e]] - wgt[rev[e]] * Hin[rev[e]]     K=512, add=h0[row]
// MODE 3: A row i = [V[i] ; agg[i]]                             K=645, add=bias[col]
template <int MODE>
__global__ __launch_bounds__(256)
void gemm_k(const float* __restrict__ Hin,
            const float* __restrict__ W,
            const float* __restrict__ Vf,
            const float* __restrict__ Eb,
            const int* __restrict__ src,
            const int* __restrict__ rev,
            const float* __restrict__ wgt,
            const float* __restrict__ agg,
            const float* __restrict__ h0,
            const float* __restrict__ bias,
            float* __restrict__ C,
            int M, int K)
{
    __shared__ __align__(16) float As[8][132];
    __shared__ __align__(16) float Bs[8][128];

    const int tid   = threadIdx.x;
    const int row_l = tid >> 1;            // 0..127 (A row within tile, also B col)
    const int k_l   = (tid & 1) * 4;       // 0 or 4
    const int grow  = blockIdx.x * 128 + row_l;
    const int jb    = blockIdx.y * 128;
    const bool rowok = (grow < M);

    // per-row gather metadata (constant across K loop)
    int   sidx = 0, ridx = 0;
    float wr   = 0.f;
    if (MODE == 1) { if (rowok) sidx = src[grow]; }
    if (MODE == 2) { if (rowok) { sidx = src[grow]; ridx = rev[grow]; wr = wgt[ridx]; } }

    const int tm0 = (tid >> 4) * 8;
    const int tn0 = (tid & 15) * 8;

    float acc[8][8];
#pragma unroll
    for (int i = 0; i < 8; i++)
#pragma unroll
        for (int j = 0; j < 8; j++) acc[i][j] = 0.f;

    for (int kb = 0; kb < K; kb += 8) {
        // ---- A tile (fused gather / message formation) ----
        float a[4];
        if (MODE == 2) {
            if (rowok) {
                float4 ag = *(const float4*)(agg + (size_t)sidx * HID + kb + k_l);
                float4 hh = *(const float4*)(Hin + (size_t)ridx * HID + kb + k_l);
                a[0] = ag.x - wr * hh.x;  a[1] = ag.y - wr * hh.y;
                a[2] = ag.z - wr * hh.z;  a[3] = ag.w - wr * hh.w;
            } else { a[0] = a[1] = a[2] = a[3] = 0.f; }
        } else if (MODE == 1) {
#pragma unroll
            for (int i = 0; i < 4; i++) {
                int kk = kb + k_l + i;
                float v = 0.f;
                if (rowok && kk < KIN)
                    v = (kk < AD) ? Vf[(size_t)sidx * AD + kk]
                                  : Eb[(size_t)grow * BD + (kk - AD)];
                a[i] = v;
            }
        } else { // MODE 3
#pragma unroll
            for (int i = 0; i < 4; i++) {
                int kk = kb + k_l + i;
                float v = 0.f;
                if (rowok && kk < KOUT)
                    v = (kk < AD) ? Vf[(size_t)grow * AD + kk]
                                  : agg[(size_t)grow * HID + (kk - AD)];
                a[i] = v;
            }
        }
        As[k_l + 0][row_l] = a[0];
        As[k_l + 1][row_l] = a[1];
        As[k_l + 2][row_l] = a[2];
        As[k_l + 3][row_l] = a[3];

        // ---- B tile: W[N,K] row-major, Bs[k][j] ----
#pragma unroll
        for (int i = 0; i < 4; i++) {
            int kk = kb + k_l + i;
            Bs[k_l + i][row_l] = (kk < K) ? W[(size_t)(jb + row_l) * K + kk] : 0.f;
        }
        __syncthreads();

#pragma unroll
        for (int k = 0; k < 8; k++) {
            float4 a0 = *(const float4*)&As[k][tm0];
            float4 a1 = *(const float4*)&As[k][tm0 + 4];
            float4 b0 = *(const float4*)&Bs[k][tn0];
            float4 b1 = *(const float4*)&Bs[k][tn0 + 4];
            float av[8] = {a0.x, a0.y, a0.z, a0.w, a1.x, a1.y, a1.z, a1.w};
            float bv[8] = {b0.x, b0.y, b0.z, b0.w, b1.x, b1.y, b1.z, b1.w};
#pragma unroll
            for (int i = 0; i < 8; i++)
#pragma unroll
                for (int j = 0; j < 8; j++)
                    acc[i][j] += av[i] * bv[j];
        }
        __syncthreads();
    }

    // ---- epilogue: add + relu, float4 stores ----
#pragma unroll
    for (int i = 0; i < 8; i++) {
        int gr = blockIdx.x * 128 + tm0 + i;
        if (gr >= M) break;
        size_t base = (size_t)gr * HID + jb + tn0;
#pragma unroll
        for (int j4 = 0; j4 < 2; j4++) {
            float4 v;
            v.x = acc[i][j4 * 4 + 0];
            v.y = acc[i][j4 * 4 + 1];
            v.z = acc[i][j4 * 4 + 2];
            v.w = acc[i][j4 * 4 + 3];
            if (MODE == 2) {
                float4 r = *(const float4*)(h0 + base + j4 * 4);
                v.x += r.x; v.y += r.y; v.z += r.z; v.w += r.w;
            }
            if (MODE == 3) {
                const float* bp = bias + jb + tn0 + j4 * 4;
                v.x += bp[0]; v.y += bp[1]; v.z += bp[2]; v.w += bp[3];
            }
            v.x = fmaxf(v.x, 0.f); v.y = fmaxf(v.y, 0.f);
            v.z = fmaxf(v.z, 0.f); v.w = fmaxf(v.w, 0.f);
            *(float4*)(C + base + j4 * 4) = v;
        }
    }
}

// ---------------- driver -----------------------------------------------------
extern "C" void kernel_launch(void* const* d_in, const int* in_sizes, int n_in,
                              void* d_out, int out_size)
{
    const float* V     = (const float*)d_in[0];
    const float* E     = (const float*)d_in[1];
    const int*   eidx  = (const int*)d_in[2];   // int32 (JAX default x64 disabled)
    const int*   rev   = (const int*)d_in[3];
    const int*   batch = (const int*)d_in[4];
    const float* wgt   = (const float*)d_in[5];
    const float* W_i   = (const float*)d_in[6];
    const float* W_h   = (const float*)d_in[7];
    const float* W_o   = (const float*)d_in[8];
    const float* b_o   = (const float*)d_in[9];

    const int* src = eidx;
    const int* dst = eidx + NEDGE;
    float* out = (float*)d_out;

    float *h0, *hA, *hB, *agg;
    cudaGetSymbolAddress((void**)&h0,  g_h0);
    cudaGetSymbolAddress((void**)&hA,  g_hA);
    cudaGetSymbolAddress((void**)&hB,  g_hB);
    cudaGetSymbolAddress((void**)&agg, g_agg);

    const dim3 blk(256);
    const dim3 grid_e((NEDGE + 127) / 128, 4);  // edge GEMMs
    const dim3 grid_a((NA    + 127) / 128, 4);  // atom GEMM
    const int  aggN4    = (NA * HID) / 4;
    const int  zeroGrid = (aggN4 + 255) / 256;
    const int  scatGrid = (NEDGE * 128 + 255) / 256;

    // 1) h0 = relu([V[src];E] @ W_i^T)
    gemm_k<1><<<grid_e, blk>>>(nullptr, W_i, V, E, src, nullptr, nullptr,
                               nullptr, nullptr, nullptr, h0, NEDGE, KIN);

    // 2) three message-passing steps (ping-pong h buffers)
    const float* hin = h0;
    float* houts[3] = { hA, hB, hA };
    for (int t = 0; t < 3; t++) {
        zero_k<<<zeroGrid, blk>>>((float4*)agg, aggN4);
        scatter_k<<<scatGrid, blk>>>(hin, dst, wgt, agg);
        gemm_k<2><<<grid_e, blk>>>(hin, W_h, nullptr, nullptr, src, rev, wgt,
                                   agg, h0, nullptr, houts[t], NEDGE, HID);
        hin = houts[t];
    }
    float* hFinal = hA;

    // 3) final aggregation (unweighted)
    zero_k<<<zeroGrid, blk>>>((float4*)agg, aggN4);
    scatter_k<<<scatGrid, blk>>>(hFinal, dst, nullptr, agg);

    // 4) h_atom = relu([V;agg] @ W_o^T + b_o) -> d_out[0 : 51.2M)
    gemm_k<3><<<grid_a, blk>>>(nullptr, W_o, V, nullptr, nullptr, nullptr,
                               nullptr, agg, nullptr, b_o, out, NA, KOUT);

    // 5) atom_batch as float -> d_out[51.2M : 51.3M)
    batch_k<<<(NA + 255) / 256, blk>>>(batch, out + (size_t)NA * HID);

    // 6) h -> d_out[51.3M : 153.7M)
    const int hN4 = (NEDGE * HID) / 4;
    copy4_k<<<(hN4 + 255) / 256, blk>>>((const float4*)hFinal,
                                        (float4*)(out + (size_t)NA * HID + NA), hN4);
}